// round 6
// baseline (speedup 1.0000x reference)
#include <cuda_runtime.h>
#include <cstdint>
#include <math_constants.h>

#define NS     16
#define NP     2048
#define DIMS   64
#define KNN    16
#define SPLIT  2
#define JRANGE (NP / SPLIT)     // 1024
#define TJ     32               // j-rows per tile
#define NT     (JRANGE / TJ)    // 32 tiles
#define BUF    4
#define PAD    68               // padded row stride in floats (16B-aligned, bank-spread)

typedef unsigned long long ull;

// partial top-K scratch: [half][ (b*NP+i)*KNN + k ]
__device__ float g_pd[SPLIT][NS * NP * KNN];
__device__ int   g_pi[SPLIT][NS * NP * KNN];

static __device__ __forceinline__ void upk(float& lo, float& hi_, ull v) {
    asm("mov.b64 {%0, %1}, %2;" : "=f"(lo), "=f"(hi_) : "l"(v));
}
static __device__ __forceinline__ void ffma2(ull& d, ull a, ull b) {
    asm("fma.rn.f32x2 %0, %1, %2, %3;" : "=l"(d) : "l"(a), "l"(b), "l"(d));
}
static __device__ __forceinline__ void fadd2(ull& d, ull a, ull b) {
    asm("add.rn.f32x2 %0, %1, %2;" : "=l"(d) : "l"(a), "l"(b));
}

// replace-max insert into unsorted top-K (strict <; ascending j handles ties)
static __device__ __forceinline__ void insert16(float bd[KNN], int bi[KNN],
                                                float& worst, int& wslot,
                                                float d, int j) {
    if (d < worst) {
        #pragma unroll
        for (int k = 0; k < KNN; ++k)
            if (k == wslot) { bd[k] = d; bi[k] = j; }
        float mv = bd[0]; int mj = bi[0]; int ms = 0;
        #pragma unroll
        for (int k = 1; k < KNN; ++k) {
            bool g = (bd[k] > mv) || (bd[k] == mv && bi[k] > mj);
            if (g) { mv = bd[k]; mj = bi[k]; ms = k; }
        }
        worst = mv; wslot = ms;
    }
}

__global__ __launch_bounds__(32, 13)
void knn_part(const float* __restrict__ h) {
    const int lane = threadIdx.x;
    const int b    = blockIdx.x;
    const int i    = blockIdx.y * 32 + lane;
    const int z    = blockIdx.z;                  // j-half
    const float* __restrict__ hb = h + (size_t)b * NP * DIMS;

    __shared__ float sj[TJ * PAD];                // padded tile (~8.7 KB)
    __shared__ float sx2[TJ];

    // ---- own i-row into registers (as f32x2 pairs) + ||h_i||^2 ----
    ull hr[DIMS / 2];
    {
        const ulonglong2* rp = reinterpret_cast<const ulonglong2*>(hb + (size_t)i * DIMS);
        #pragma unroll
        for (int d = 0; d < DIMS / 4; ++d) {
            ulonglong2 t = rp[d];
            hr[2 * d] = t.x; hr[2 * d + 1] = t.y;
        }
    }
    float x2i;
    {
        ull s0 = 0ull, s1 = 0ull;
        #pragma unroll
        for (int d = 0; d < DIMS / 4; ++d) {
            ffma2(s0, hr[2 * d],     hr[2 * d]);
            ffma2(s1, hr[2 * d + 1], hr[2 * d + 1]);
        }
        fadd2(s0, s0, s1);
        float lo, hi; upk(lo, hi, s0);
        x2i = lo + hi;
    }

    // ---- top-K over m = x2j - 2*dot (x2i added at emit) ----
    float bd[KNN]; int bi[KNN];
    #pragma unroll
    for (int k = 0; k < KNN; ++k) { bd[k] = CUDART_INF_F; bi[k] = 0x7fffffff; }
    float worst = CUDART_INF_F; int wslot = 0;
    float cd[BUF]; int cj[BUF]; int c = 0;
    #pragma unroll
    for (int s = 0; s < BUF; ++s) { cd[s] = 0.f; cj[s] = 0; }

    const int jbase0 = z * JRANGE;
    for (int t = 0; t < NT; ++t) {
        const int jb = jbase0 + t * TJ;
        __syncwarp();
        // cooperative coalesced tile load: 512 float4, 16 per thread
        {
            const float4* g4 = reinterpret_cast<const float4*>(hb + (size_t)jb * DIMS);
            #pragma unroll
            for (int u = 0; u < 16; ++u) {
                int f   = u * 32 + lane;           // flat float4 index
                int row = f >> 4, cc = f & 15;
                *reinterpret_cast<float4*>(&sj[row * PAD + cc * 4]) = g4[f];
            }
        }
        __syncwarp();
        // per-row sumsq (thread lane -> row lane; padded stride = spread banks)
        {
            ull s0 = 0ull, s1 = 0ull;
            const float* rowp = &sj[lane * PAD];
            #pragma unroll
            for (int d = 0; d < DIMS / 4; ++d) {
                ulonglong2 v = *reinterpret_cast<const ulonglong2*>(rowp + d * 4);
                ffma2(s0, v.x, v.x);
                ffma2(s1, v.y, v.y);
            }
            fadd2(s0, s0, s1);
            float lo, hi; upk(lo, hi, s0);
            sx2[lane] = lo + hi;
        }
        __syncwarp();

        #pragma unroll 8
        for (int jj = 0; jj < TJ; ++jj) {
            const float* rowp = &sj[jj * PAD];     // broadcast reads
            ull a0 = 0ull, a1 = 0ull, a2 = 0ull, a3 = 0ull;
            #pragma unroll
            for (int d = 0; d < DIMS / 8; ++d) {
                ulonglong2 v = *reinterpret_cast<const ulonglong2*>(rowp + d * 8);
                ulonglong2 w = *reinterpret_cast<const ulonglong2*>(rowp + d * 8 + 4);
                ffma2(a0, hr[4 * d],     v.x);
                ffma2(a1, hr[4 * d + 1], v.y);
                ffma2(a2, hr[4 * d + 2], w.x);
                ffma2(a3, hr[4 * d + 3], w.y);
            }
            fadd2(a0, a0, a1);
            fadd2(a2, a2, a3);
            fadd2(a0, a0, a2);
            float lo, hi; upk(lo, hi, a0);
            const float dot = lo + hi;
            const float m   = fmaf(-2.0f, dot, sx2[jj]);
            const int   jg  = jb + jj;

            if (m < worst) {                       // cheap filter into buffer
                #pragma unroll
                for (int s = 0; s < BUF; ++s)
                    if (s == c) { cd[s] = m; cj[s] = jg; }
                ++c;
                if (c == BUF) {                    // per-thread drain (rare)
                    #pragma unroll
                    for (int s = 0; s < BUF; ++s)
                        insert16(bd, bi, worst, wslot, cd[s], cj[s]);
                    c = 0;
                }
            }
        }
    }
    // final drain
    #pragma unroll
    for (int s = 0; s < BUF; ++s)
        if (s < c) insert16(bd, bi, worst, wslot, cd[s], cj[s]);

    // ---- emit partial (true dist = x2i + m), unsorted ----
    const size_t base = ((size_t)b * NP + i) * KNN;
    #pragma unroll
    for (int k = 0; k < KNN; ++k) {
        g_pd[z][base + k] = x2i + bd[k];
        g_pi[z][base + k] = bi[k];
    }
}

__global__ __launch_bounds__(128)
void knn_merge(float* __restrict__ out) {
    const int r = blockIdx.x * 128 + threadIdx.x;   // global row = b*NP + i
    const int b = r / NP;
    const int i = r - b * NP;

    float fd[KNN]; int fi[KNN];
    #pragma unroll
    for (int k = 0; k < KNN; ++k) { fd[k] = CUDART_INF_F; fi[k] = 0x7fffffff; }
    float wst = CUDART_INF_F; int wsl = 0;

    const size_t base = (size_t)r * KNN;
    #pragma unroll
    for (int z = 0; z < SPLIT; ++z) {
        #pragma unroll
        for (int k = 0; k < KNN; ++k) {
            float d = g_pd[z][base + k];
            int   j = g_pi[z][base + k];
            // lexicographic accept (handles dist ties across halves)
            if (d < wst || (d == wst && j < fi[wsl])) {
                #pragma unroll
                for (int s = 0; s < KNN; ++s)
                    if (s == wsl) { fd[s] = d; fi[s] = j; }
                float mv = fd[0]; int mj = fi[0]; int ms = 0;
                #pragma unroll
                for (int s = 1; s < KNN; ++s) {
                    bool g = (fd[s] > mv) || (fd[s] == mv && fi[s] > mj);
                    if (g) { mv = fd[s]; mj = fi[s]; ms = s; }
                }
                wst = mv; wsl = ms;
            }
        }
    }
    // sort ascending by (dist, idx): odd-even, 16 passes
    #pragma unroll
    for (int p = 0; p < KNN; ++p) {
        #pragma unroll
        for (int k = (p & 1); k + 1 < KNN; k += 2) {
            bool sw = (fd[k] > fd[k + 1]) || (fd[k] == fd[k + 1] && fi[k] > fi[k + 1]);
            if (sw) {
                float td = fd[k]; fd[k] = fd[k + 1]; fd[k + 1] = td;
                int   ti = fi[k]; fi[k] = fi[k + 1]; fi[k + 1] = ti;
            }
        }
    }
    // emit [knn_dist | dst | src]
    const size_t sect = (size_t)NS * NP * KNN;
    float* od   = out + base;
    float* odst = out + sect + base;
    float* osrc = out + 2 * sect + base;
    const int off = b * NP;
    #pragma unroll
    for (int k = 0; k < KNN; ++k) {
        od[k]   = fd[k];
        odst[k] = (float)(fi[k] + off);
        osrc[k] = (float)(i + off);
    }
}

extern "C" void kernel_launch(void* const* d_in, const int* in_sizes, int n_in,
                              void* d_out, int out_size) {
    (void)in_sizes; (void)n_in; (void)out_size;
    const float* h = (const float*)d_in[0];   // (16, 2048, 64) fp32; K=16 hardcoded
    float* out = (float*)d_out;
    dim3 g1(NS, NP / 32, SPLIT);
    knn_part<<<g1, 32>>>(h);
    knn_merge<<<(NS * NP) / 128, 128>>>(out);
}

// round 7
// speedup vs baseline: 1.6841x; 1.6841x over previous
#include <cuda_runtime.h>
#include <cstdint>
#include <math_constants.h>

#define NS     16
#define NP     2048
#define DIMS   64
#define KNN    16
#define SPLIT  2
#define JRANGE (NP / SPLIT)     // 1024
#define TJ     32               // j-rows per tile
#define NT     (JRANGE / TJ)    // 32 tiles
#define BUF    4
#define PAD    68               // padded row stride in floats (16B-aligned, bank-spread)

typedef unsigned long long ull;

// partial top-K scratch: [half][ (b*NP+i)*KNN + k ]
__device__ float g_pd[SPLIT][NS * NP * KNN];
__device__ int   g_pi[SPLIT][NS * NP * KNN];

static __device__ __forceinline__ void upk(float& lo, float& hi_, ull v) {
    asm("mov.b64 {%0, %1}, %2;" : "=f"(lo), "=f"(hi_) : "l"(v));
}
static __device__ __forceinline__ void ffma2(ull& d, ull a, ull b) {
    asm("fma.rn.f32x2 %0, %1, %2, %3;" : "=l"(d) : "l"(a), "l"(b), "l"(d));
}
static __device__ __forceinline__ void fadd2(ull& d, ull a, ull b) {
    asm("add.rn.f32x2 %0, %1, %2;" : "=l"(d) : "l"(a), "l"(b));
}

// replace-max insert into unsorted top-K (strict <; ascending j handles ties)
static __device__ __forceinline__ void insert16(float bd[KNN], int bi[KNN],
                                                float& worst, int& wslot,
                                                float d, int j) {
    if (d < worst) {
        #pragma unroll
        for (int k = 0; k < KNN; ++k)
            if (k == wslot) { bd[k] = d; bi[k] = j; }
        float mv = bd[0]; int mj = bi[0]; int ms = 0;
        #pragma unroll
        for (int k = 1; k < KNN; ++k) {
            bool g = (bd[k] > mv) || (bd[k] == mv && bi[k] > mj);
            if (g) { mv = bd[k]; mj = bi[k]; ms = k; }
        }
        worst = mv; wslot = ms;
    }
}

__global__ __launch_bounds__(32)   // NO min-blocks clause: do not cap registers
void knn_part(const float* __restrict__ h) {
    const int lane = threadIdx.x;
    const int b    = blockIdx.x;
    const int i    = blockIdx.y * 32 + lane;
    const int z    = blockIdx.z;                  // j-half
    const float* __restrict__ hb = h + (size_t)b * NP * DIMS;

    __shared__ float sj[TJ * PAD];                // padded tile (~8.7 KB)
    __shared__ float sx2[TJ];

    // ---- own i-row into registers (as f32x2 pairs) + ||h_i||^2 ----
    ull hr[DIMS / 2];
    {
        const ulonglong2* rp = reinterpret_cast<const ulonglong2*>(hb + (size_t)i * DIMS);
        #pragma unroll
        for (int d = 0; d < DIMS / 4; ++d) {
            ulonglong2 t = rp[d];
            hr[2 * d] = t.x; hr[2 * d + 1] = t.y;
        }
    }
    float x2i;
    {
        ull s0 = 0ull, s1 = 0ull;
        #pragma unroll
        for (int d = 0; d < DIMS / 4; ++d) {
            ffma2(s0, hr[2 * d],     hr[2 * d]);
            ffma2(s1, hr[2 * d + 1], hr[2 * d + 1]);
        }
        fadd2(s0, s0, s1);
        float lo, hi; upk(lo, hi, s0);
        x2i = lo + hi;
    }

    // ---- top-K over m = x2j - 2*dot (x2i added at emit) ----
    float bd[KNN]; int bi[KNN];
    #pragma unroll
    for (int k = 0; k < KNN; ++k) { bd[k] = CUDART_INF_F; bi[k] = 0x7fffffff; }
    float worst = CUDART_INF_F; int wslot = 0;
    float cd[BUF]; int cj[BUF]; int c = 0;
    #pragma unroll
    for (int s = 0; s < BUF; ++s) { cd[s] = 0.f; cj[s] = 0; }

    const int jbase0 = z * JRANGE;
    for (int t = 0; t < NT; ++t) {
        const int jb = jbase0 + t * TJ;
        __syncwarp();
        // cooperative coalesced tile load: 512 float4, 16 per thread
        {
            const float4* g4 = reinterpret_cast<const float4*>(hb + (size_t)jb * DIMS);
            #pragma unroll
            for (int u = 0; u < 16; ++u) {
                int f   = u * 32 + lane;           // flat float4 index
                int row = f >> 4, cc = f & 15;
                *reinterpret_cast<float4*>(&sj[row * PAD + cc * 4]) = g4[f];
            }
        }
        __syncwarp();
        // per-row sumsq (thread lane -> row lane; padded stride = spread banks)
        {
            ull s0 = 0ull, s1 = 0ull;
            const float* rowp = &sj[lane * PAD];
            #pragma unroll
            for (int d = 0; d < DIMS / 4; ++d) {
                ulonglong2 v = *reinterpret_cast<const ulonglong2*>(rowp + d * 4);
                ffma2(s0, v.x, v.x);
                ffma2(s1, v.y, v.y);
            }
            fadd2(s0, s0, s1);
            float lo, hi; upk(lo, hi, s0);
            sx2[lane] = lo + hi;
        }
        __syncwarp();

        #pragma unroll 4
        for (int jj = 0; jj < TJ; ++jj) {
            const float* rowp = &sj[jj * PAD];     // broadcast reads
            ull a0 = 0ull, a1 = 0ull, a2 = 0ull, a3 = 0ull;
            #pragma unroll
            for (int d = 0; d < DIMS / 8; ++d) {
                ulonglong2 v = *reinterpret_cast<const ulonglong2*>(rowp + d * 8);
                ulonglong2 w = *reinterpret_cast<const ulonglong2*>(rowp + d * 8 + 4);
                ffma2(a0, hr[4 * d],     v.x);
                ffma2(a1, hr[4 * d + 1], v.y);
                ffma2(a2, hr[4 * d + 2], w.x);
                ffma2(a3, hr[4 * d + 3], w.y);
            }
            fadd2(a0, a0, a1);
            fadd2(a2, a2, a3);
            fadd2(a0, a0, a2);
            float lo, hi; upk(lo, hi, a0);
            const float dot = lo + hi;
            const float m   = fmaf(-2.0f, dot, sx2[jj]);
            const int   jg  = jb + jj;

            if (m < worst) {                       // cheap filter into buffer
                #pragma unroll
                for (int s = 0; s < BUF; ++s)
                    if (s == c) { cd[s] = m; cj[s] = jg; }
                ++c;
                if (c == BUF) {                    // per-thread drain (rare)
                    #pragma unroll
                    for (int s = 0; s < BUF; ++s)
                        insert16(bd, bi, worst, wslot, cd[s], cj[s]);
                    c = 0;
                }
            }
        }
    }
    // final drain
    #pragma unroll
    for (int s = 0; s < BUF; ++s)
        if (s < c) insert16(bd, bi, worst, wslot, cd[s], cj[s]);

    // ---- emit partial (true dist = x2i + m), unsorted ----
    const size_t base = ((size_t)b * NP + i) * KNN;
    #pragma unroll
    for (int k = 0; k < KNN; ++k) {
        g_pd[z][base + k] = x2i + bd[k];
        g_pi[z][base + k] = bi[k];
    }
}

__global__ __launch_bounds__(128)
void knn_merge(float* __restrict__ out) {
    const int r = blockIdx.x * 128 + threadIdx.x;   // global row = b*NP + i
    const int b = r / NP;
    const int i = r - b * NP;

    float fd[KNN]; int fi[KNN];
    #pragma unroll
    for (int k = 0; k < KNN; ++k) { fd[k] = CUDART_INF_F; fi[k] = 0x7fffffff; }
    float wst = CUDART_INF_F; int wsl = 0;

    const size_t base = (size_t)r * KNN;
    #pragma unroll
    for (int z = 0; z < SPLIT; ++z) {
        // vectorized list reads: 4x float4 / int4 per half
        float4 dv[4]; int4 jv[4];
        #pragma unroll
        for (int u = 0; u < 4; ++u) {
            dv[u] = *reinterpret_cast<const float4*>(&g_pd[z][base + 4 * u]);
            jv[u] = *reinterpret_cast<const int4*>  (&g_pi[z][base + 4 * u]);
        }
        const float* dp = reinterpret_cast<const float*>(dv);
        const int*   jp = reinterpret_cast<const int*>(jv);
        #pragma unroll
        for (int k = 0; k < KNN; ++k) {
            float d = dp[k];
            int   j = jp[k];
            // lexicographic accept (handles dist ties across halves)
            if (d < wst || (d == wst && j < fi[wsl])) {
                #pragma unroll
                for (int s = 0; s < KNN; ++s)
                    if (s == wsl) { fd[s] = d; fi[s] = j; }
                float mv = fd[0]; int mj = fi[0]; int ms = 0;
                #pragma unroll
                for (int s = 1; s < KNN; ++s) {
                    bool g = (fd[s] > mv) || (fd[s] == mv && fi[s] > mj);
                    if (g) { mv = fd[s]; mj = fi[s]; ms = s; }
                }
                wst = mv; wsl = ms;
            }
        }
    }
    // sort ascending by (dist, idx): odd-even, 16 passes
    #pragma unroll
    for (int p = 0; p < KNN; ++p) {
        #pragma unroll
        for (int k = (p & 1); k + 1 < KNN; k += 2) {
            bool sw = (fd[k] > fd[k + 1]) || (fd[k] == fd[k + 1] && fi[k] > fi[k + 1]);
            if (sw) {
                float td = fd[k]; fd[k] = fd[k + 1]; fd[k + 1] = td;
                int   ti = fi[k]; fi[k] = fi[k + 1]; fi[k + 1] = ti;
            }
        }
    }
    // emit [knn_dist | dst | src]
    const size_t sect = (size_t)NS * NP * KNN;
    float* od   = out + base;
    float* odst = out + sect + base;
    float* osrc = out + 2 * sect + base;
    const int off = b * NP;
    #pragma unroll
    for (int k = 0; k < KNN; ++k) {
        od[k]   = fd[k];
        odst[k] = (float)(fi[k] + off);
        osrc[k] = (float)(i + off);
    }
}

extern "C" void kernel_launch(void* const* d_in, const int* in_sizes, int n_in,
                              void* d_out, int out_size) {
    (void)in_sizes; (void)n_in; (void)out_size;
    const float* h = (const float*)d_in[0];   // (16, 2048, 64) fp32; K=16 hardcoded
    float* out = (float*)d_out;
    dim3 g1(NS, NP / 32, SPLIT);
    knn_part<<<g1, 32>>>(h);
    knn_merge<<<(NS * NP) / 128, 128>>>(out);
}

// round 9
// speedup vs baseline: 12.4393x; 7.3863x over previous
#include <cuda_runtime.h>
#include <math_constants.h>

#define NS     16
#define NP     2048
#define DIMS   64
#define KNN    16
#define TI     32    // one warp per block
#define TJ     64    // j-rows per shared tile
#define SPLIT  2
#define JRANGE (NP / SPLIT)   // 1024
#define BUF    4     // candidate buffer slots per lane

typedef unsigned long long ull;

// partial top-K scratch: [half][(b*NP+i)*KNN + k]
__device__ float g_pd[SPLIT][NS * NP * KNN];
__device__ int   g_pi[SPLIT][NS * NP * KNN];

__device__ __forceinline__ void upk(float &lo, float &hi_, ull v) {
    asm("mov.b64 {%0, %1}, %2;" : "=f"(lo), "=f"(hi_) : "l"(v));
}
__device__ __forceinline__ void ffma2(ull &d, ull a, ull b) {
    asm("fma.rn.f32x2 %0, %1, %2, %3;" : "=l"(d) : "l"(a), "l"(b), "l"(d));
}

// replace-max insert into unsorted top-K kept in registers
__device__ __forceinline__ void insert16(float bd[KNN], int bidx[KNN],
                                         float &worst, int &wslot,
                                         float d, int j) {
    if (d < worst) {
        #pragma unroll
        for (int k = 0; k < KNN; ++k) {
            if (k == wslot) { bd[k] = d; bidx[k] = j; }
        }
        float mv = bd[0]; int mj = bidx[0]; int ms = 0;
        #pragma unroll
        for (int k = 1; k < KNN; ++k) {
            bool g = (bd[k] > mv) || (bd[k] == mv && bidx[k] > mj);
            if (g) { mv = bd[k]; mj = bidx[k]; ms = k; }
        }
        worst = mv; wslot = ms;
    }
}

__global__ __launch_bounds__(TI)
void knn_part(const float* __restrict__ h) {
    const int b = blockIdx.x;
    const int i = blockIdx.y * TI + threadIdx.x;
    const int z = blockIdx.z;                       // j-half
    const float* __restrict__ hb = h + (size_t)b * NP * DIMS;

    __shared__ ulonglong2 sj[TJ][DIMS / 4];   // 16 KB, 16B-aligned rows
    __shared__ float sx2[TJ];

    // ---- this thread's i-row, packed as f32x2 pairs ----
    ull hr[DIMS / 2];
    const ulonglong2* hrow = reinterpret_cast<const ulonglong2*>(hb + (size_t)i * DIMS);
    #pragma unroll
    for (int d = 0; d < DIMS / 4; ++d) { ulonglong2 t = hrow[d]; hr[2*d] = t.x; hr[2*d+1] = t.y; }
    float x2i = 0.0f;
    #pragma unroll
    for (int d = 0; d < DIMS / 2; ++d) { float a, c; upk(a, c, hr[d]); x2i += a*a + c*c; }

    // ---- unsorted top-K + max tracking ----
    float bd[KNN]; int bidx[KNN];
    #pragma unroll
    for (int k = 0; k < KNN; ++k) { bd[k] = CUDART_INF_F; bidx[k] = 0x7fffffff; }
    float worst = CUDART_INF_F; int wslot = 0;

    // ---- candidate buffer ----
    float cd[BUF]; int cj[BUF]; int c = 0;
    #pragma unroll
    for (int s = 0; s < BUF; ++s) { cd[s] = 0.f; cj[s] = 0; }

    const int jend = (z + 1) * JRANGE;
    for (int j0 = z * JRANGE; j0 < jend; j0 += TJ) {
        __syncwarp();
        // cooperative tile load (128-bit, linear)
        {
            ulonglong2*       s4 = &sj[0][0];
            const ulonglong2* g4 = reinterpret_cast<const ulonglong2*>(hb + (size_t)j0 * DIMS);
            #pragma unroll
            for (int t = threadIdx.x; t < TJ * DIMS / 4; t += TI) s4[t] = g4[t];
        }
        __syncwarp();
        // ||h_j||^2 for the tile (2 rows per thread)
        #pragma unroll
        for (int r = threadIdx.x; r < TJ; r += TI) {
            float s = 0.0f;
            #pragma unroll
            for (int d = 0; d < DIMS / 4; ++d) {
                ulonglong2 v = sj[r][d];
                float a, bq, cq, e; upk(a, bq, v.x); upk(cq, e, v.y);
                s += a*a + bq*bq + cq*cq + e*e;
            }
            sx2[r] = s;
        }
        __syncwarp();

        for (int jj = 0; jj < TJ; ++jj) {
            // 64-dim dot as 32 packed FMAs, 4 independent chains
            ull a0 = 0ull, a1 = 0ull, a2 = 0ull, a3 = 0ull;  // (0.f,0.f) bit pattern
            #pragma unroll
            for (int d = 0; d < DIMS / 8; ++d) {
                ulonglong2 v = sj[jj][2*d];
                ulonglong2 w = sj[jj][2*d + 1];
                ffma2(a0, hr[4*d + 0], v.x);
                ffma2(a1, hr[4*d + 1], v.y);
                ffma2(a2, hr[4*d + 2], w.x);
                ffma2(a3, hr[4*d + 3], w.y);
            }
            float f0,f1,f2,f3,f4,f5,f6,f7;
            upk(f0, f1, a0); upk(f2, f3, a1); upk(f4, f5, a2); upk(f6, f7, a3);
            const float dot  = ((f0 + f1) + (f2 + f3)) + ((f4 + f5) + (f6 + f7));
            const float dist = fmaf(-2.0f, dot, x2i + sx2[jj]);
            const int   jg   = j0 + jj;

            // cheap filter into buffer (strict <; ascending j handles ties)
            const bool take = dist < worst;
            if (take) {
                #pragma unroll
                for (int s = 0; s < BUF; ++s) {
                    if (s == c) { cd[s] = dist; cj[s] = jg; }
                }
                ++c;
            }
            // rare warp-wide drain
            if (__any_sync(0xffffffffu, c == BUF)) {
                #pragma unroll
                for (int s = 0; s < BUF; ++s) {
                    if (s < c) insert16(bd, bidx, worst, wslot, cd[s], cj[s]);
                }
                c = 0;
            }
        }
    }
    // final drain
    #pragma unroll
    for (int s = 0; s < BUF; ++s) {
        if (s < c) insert16(bd, bidx, worst, wslot, cd[s], cj[s]);
    }

    // ---- emit partial (unsorted) to scratch ----
    const size_t base = ((size_t)b * NP + i) * KNN;
    #pragma unroll
    for (int k = 0; k < KNN; ++k) {
        g_pd[z][base + k] = bd[k];
        g_pi[z][base + k] = bidx[k];
    }
}

__global__ __launch_bounds__(128)
void knn_merge(float* __restrict__ out) {
    const int r = blockIdx.x * 128 + threadIdx.x;   // global row = b*NP + i
    const int b = r / NP;
    const int i = r - b * NP;

    float fd[KNN]; int fi[KNN];
    #pragma unroll
    for (int k = 0; k < KNN; ++k) { fd[k] = CUDART_INF_F; fi[k] = 0x7fffffff; }
    float wst = CUDART_INF_F; int wsl = 0;

    const size_t base = (size_t)r * KNN;
    #pragma unroll
    for (int z = 0; z < SPLIT; ++z) {
        float4 dv[4]; int4 jv[4];
        #pragma unroll
        for (int u = 0; u < 4; ++u) {
            dv[u] = *reinterpret_cast<const float4*>(&g_pd[z][base + 4 * u]);
            jv[u] = *reinterpret_cast<const int4*>  (&g_pi[z][base + 4 * u]);
        }
        const float* dp = reinterpret_cast<const float*>(dv);
        const int*   jp = reinterpret_cast<const int*>(jv);
        #pragma unroll
        for (int k = 0; k < KNN; ++k) {
            float d = dp[k];
            int   j = jp[k];
            // lexicographic accept (handles dist ties across halves)
            if (d < wst || (d == wst && j < fi[wsl])) {
                #pragma unroll
                for (int s = 0; s < KNN; ++s)
                    if (s == wsl) { fd[s] = d; fi[s] = j; }
                float mv = fd[0]; int mj = fi[0]; int ms = 0;
                #pragma unroll
                for (int s = 1; s < KNN; ++s) {
                    bool g = (fd[s] > mv) || (fd[s] == mv && fi[s] > mj);
                    if (g) { mv = fd[s]; mj = fi[s]; ms = s; }
                }
                wst = mv; wsl = ms;
            }
        }
    }
    // sort ascending by (dist, idx): odd-even, 16 passes
    #pragma unroll
    for (int p = 0; p < KNN; ++p) {
        #pragma unroll
        for (int k = (p & 1); k + 1 < KNN; k += 2) {
            bool sw = (fd[k] > fd[k + 1]) || (fd[k] == fd[k + 1] && fi[k] > fi[k + 1]);
            if (sw) {
                float td = fd[k]; fd[k] = fd[k + 1]; fd[k + 1] = td;
                int   ti = fi[k]; fi[k] = fi[k + 1]; fi[k + 1] = ti;
            }
        }
    }
    // emit [knn_dist | dst | src]
    const size_t sect = (size_t)NS * NP * KNN;
    float* od   = out + base;
    float* odst = out + sect + base;
    float* osrc = out + 2 * sect + base;
    const int off = b * NP;
    #pragma unroll
    for (int k = 0; k < KNN; ++k) {
        od[k]   = fd[k];
        odst[k] = (float)(fi[k] + off);
        osrc[k] = (float)(i + off);
    }
}

extern "C" void kernel_launch(void* const* d_in, const int* in_sizes, int n_in,
                              void* d_out, int out_size) {
    (void)in_sizes; (void)n_in; (void)out_size;
    const float* h = (const float*)d_in[0];   // (16, 2048, 64) fp32; K=16 hardcoded
    float* out = (float*)d_out;
    dim3 g1(NS, NP / TI, SPLIT);
    knn_part<<<g1, TI>>>(h);
    knn_merge<<<(NS * NP) / 128, 128>>>(out);
}

// round 11
// speedup vs baseline: 17.2549x; 1.3871x over previous
#include <cuda_runtime.h>
#include <math_constants.h>

#define NS     16
#define NP     2048
#define DIMS   64
#define KNN    16
#define TI     32    // one warp per block
#define TJ     32    // j-rows per shared tile
#define SPLIT  2
#define JRANGE (NP / SPLIT)   // 1024
#define BUF    4     // candidate buffer slots per lane
#define TKS    17    // per-lane top-K smem stride (conflict-free)

typedef unsigned long long ull;

// partial top-K scratch: [half][(b*NP+i)*KNN + k]
__device__ float g_pd[SPLIT][NS * NP * KNN];
__device__ int   g_pi[SPLIT][NS * NP * KNN];

__device__ __forceinline__ void upk(float &lo, float &hi_, ull v) {
    asm("mov.b64 {%0, %1}, %2;" : "=f"(lo), "=f"(hi_) : "l"(v));
}
__device__ __forceinline__ void ffma2(ull &d, ull a, ull b) {
    asm("fma.rn.f32x2 %0, %1, %2, %3;" : "=l"(d) : "l"(a), "l"(b), "l"(d));
}

// replace-max insert into unsorted top-K kept in SMEM (per-lane region)
__device__ __forceinline__ void insert16s(float* myd, int* myi,
                                          float &worst, int &wslot,
                                          float d, int j) {
    if (d < worst) {
        myd[wslot] = d;              // runtime-indexed STS (native on smem)
        myi[wslot] = j;
        float mv = myd[0]; int mj = myi[0]; int ms = 0;
        #pragma unroll
        for (int k = 1; k < KNN; ++k) {
            float vk = myd[k]; int ik = myi[k];
            bool g = (vk > mv) || (vk == mv && ik > mj);
            if (g) { mv = vk; mj = ik; ms = k; }
        }
        worst = mv; wslot = ms;
    }
}

__global__ __launch_bounds__(TI, 14)   // cap 146 regs; structural need ~132 after smem top-K
void knn_part(const float* __restrict__ h) {
    const int lane = threadIdx.x;
    const int b = blockIdx.x;
    const int i = blockIdx.y * TI + lane;
    const int z = blockIdx.z;                       // j-half
    const float* __restrict__ hb = h + (size_t)b * NP * DIMS;

    __shared__ ulonglong2 sj[TJ][DIMS / 4];   // 8 KB tile
    __shared__ float sx2[TJ];
    __shared__ float sbd[TI * TKS];           // per-lane top-K dists
    __shared__ int   sbi[TI * TKS];           // per-lane top-K indices

    float* myd = &sbd[lane * TKS];
    int*   myi = &sbi[lane * TKS];
    #pragma unroll
    for (int k = 0; k < KNN; ++k) { myd[k] = CUDART_INF_F; myi[k] = 0x7fffffff; }

    // ---- this thread's i-row, packed as f32x2 pairs ----
    ull hr[DIMS / 2];
    const ulonglong2* hrow = reinterpret_cast<const ulonglong2*>(hb + (size_t)i * DIMS);
    #pragma unroll
    for (int d = 0; d < DIMS / 4; ++d) { ulonglong2 t = hrow[d]; hr[2*d] = t.x; hr[2*d+1] = t.y; }
    float x2i = 0.0f;
    #pragma unroll
    for (int d = 0; d < DIMS / 2; ++d) { float a, c; upk(a, c, hr[d]); x2i += a*a + c*c; }

    float worst = CUDART_INF_F; int wslot = 0;

    // ---- candidate buffer ----
    float cd[BUF]; int cj[BUF]; int c = 0;
    #pragma unroll
    for (int s = 0; s < BUF; ++s) { cd[s] = 0.f; cj[s] = 0; }

    const int jend = (z + 1) * JRANGE;
    for (int j0 = z * JRANGE; j0 < jend; j0 += TJ) {
        __syncwarp();
        // cooperative tile load (128-bit, linear): 16 per lane
        {
            ulonglong2*       s4 = &sj[0][0];
            const ulonglong2* g4 = reinterpret_cast<const ulonglong2*>(hb + (size_t)j0 * DIMS);
            #pragma unroll
            for (int t = lane; t < TJ * DIMS / 4; t += TI) s4[t] = g4[t];
        }
        __syncwarp();
        // ||h_j||^2 for the tile (1 row per lane)
        {
            float s = 0.0f;
            #pragma unroll
            for (int d = 0; d < DIMS / 4; ++d) {
                ulonglong2 v = sj[lane][d];
                float a, bq, cq, e; upk(a, bq, v.x); upk(cq, e, v.y);
                s += a*a + bq*bq + cq*cq + e*e;
            }
            sx2[lane] = s;
        }
        __syncwarp();

        for (int jj = 0; jj < TJ; ++jj) {
            // 64-dim dot as 32 packed FMAs, 4 independent chains
            ull a0 = 0ull, a1 = 0ull, a2 = 0ull, a3 = 0ull;
            #pragma unroll
            for (int d = 0; d < DIMS / 8; ++d) {
                ulonglong2 v = sj[jj][2*d];
                ulonglong2 w = sj[jj][2*d + 1];
                ffma2(a0, hr[4*d + 0], v.x);
                ffma2(a1, hr[4*d + 1], v.y);
                ffma2(a2, hr[4*d + 2], w.x);
                ffma2(a3, hr[4*d + 3], w.y);
            }
            float f0,f1,f2,f3,f4,f5,f6,f7;
            upk(f0, f1, a0); upk(f2, f3, a1); upk(f4, f5, a2); upk(f6, f7, a3);
            const float dot  = ((f0 + f1) + (f2 + f3)) + ((f4 + f5) + (f6 + f7));
            const float dist = fmaf(-2.0f, dot, x2i + sx2[jj]);
            const int   jg   = j0 + jj;

            // cheap filter into register buffer (strict <; ascending j handles ties)
            if (dist < worst) {
                #pragma unroll
                for (int s = 0; s < BUF; ++s) {
                    if (s == c) { cd[s] = dist; cj[s] = jg; }
                }
                ++c;
            }
            // rare warp-wide drain
            if (__any_sync(0xffffffffu, c == BUF)) {
                #pragma unroll
                for (int s = 0; s < BUF; ++s) {
                    if (s < c) insert16s(myd, myi, worst, wslot, cd[s], cj[s]);
                }
                c = 0;
            }
        }
    }
    // final drain
    #pragma unroll
    for (int s = 0; s < BUF; ++s) {
        if (s < c) insert16s(myd, myi, worst, wslot, cd[s], cj[s]);
    }

    // ---- emit partial (unsorted) to scratch ----
    const size_t base = ((size_t)b * NP + i) * KNN;
    #pragma unroll
    for (int k = 0; k < KNN; ++k) {
        g_pd[z][base + k] = myd[k];
        g_pi[z][base + k] = myi[k];
    }
}

__global__ __launch_bounds__(128)
void knn_merge(float* __restrict__ out) {
    const int r = blockIdx.x * 128 + threadIdx.x;   // global row = b*NP + i
    const int b = r / NP;
    const int i = r - b * NP;

    float fd[KNN]; int fi[KNN];
    #pragma unroll
    for (int k = 0; k < KNN; ++k) { fd[k] = CUDART_INF_F; fi[k] = 0x7fffffff; }
    float wst = CUDART_INF_F; int wsl = 0;

    const size_t base = (size_t)r * KNN;
    #pragma unroll
    for (int z = 0; z < SPLIT; ++z) {
        float4 dv[4]; int4 jv[4];
        #pragma unroll
        for (int u = 0; u < 4; ++u) {
            dv[u] = *reinterpret_cast<const float4*>(&g_pd[z][base + 4 * u]);
            jv[u] = *reinterpret_cast<const int4*>  (&g_pi[z][base + 4 * u]);
        }
        const float* dp = reinterpret_cast<const float*>(dv);
        const int*   jp = reinterpret_cast<const int*>(jv);
        #pragma unroll
        for (int k = 0; k < KNN; ++k) {
            float d = dp[k];
            int   j = jp[k];
            // lexicographic accept (handles dist ties across halves)
            if (d < wst || (d == wst && j < fi[wsl])) {
                #pragma unroll
                for (int s = 0; s < KNN; ++s)
                    if (s == wsl) { fd[s] = d; fi[s] = j; }
                float mv = fd[0]; int mj = fi[0]; int ms = 0;
                #pragma unroll
                for (int s = 1; s < KNN; ++s) {
                    bool g = (fd[s] > mv) || (fd[s] == mv && fi[s] > mj);
                    if (g) { mv = fd[s]; mj = fi[s]; ms = s; }
                }
                wst = mv; wsl = ms;
            }
        }
    }
    // sort ascending by (dist, idx): odd-even, 16 passes
    #pragma unroll
    for (int p = 0; p < KNN; ++p) {
        #pragma unroll
        for (int k = (p & 1); k + 1 < KNN; k += 2) {
            bool sw = (fd[k] > fd[k + 1]) || (fd[k] == fd[k + 1] && fi[k] > fi[k + 1]);
            if (sw) {
                float td = fd[k]; fd[k] = fd[k + 1]; fd[k + 1] = td;
                int   ti = fi[k]; fi[k] = fi[k + 1]; fi[k + 1] = ti;
            }
        }
    }
    // emit [knn_dist | dst | src]
    const size_t sect = (size_t)NS * NP * KNN;
    float* od   = out + base;
    float* odst = out + sect + base;
    float* osrc = out + 2 * sect + base;
    const int off = b * NP;
    #pragma unroll
    for (int k = 0; k < KNN; ++k) {
        od[k]   = fd[k];
        odst[k] = (float)(fi[k] + off);
        osrc[k] = (float)(i + off);
    }
}

extern "C" void kernel_launch(void* const* d_in, const int* in_sizes, int n_in,
                              void* d_out, int out_size) {
    (void)in_sizes; (void)n_in; (void)out_size;
    const float* h = (const float*)d_in[0];   // (16, 2048, 64) fp32; K=16 hardcoded
    float* out = (float*)d_out;
    dim3 g1(NS, NP / TI, SPLIT);
    knn_part<<<g1, TI>>>(h);
    knn_merge<<<(NS * NP) / 128, 128>>>(out);
}

// round 15
// speedup vs baseline: 21.2789x; 1.2332x over previous
#include <cuda_runtime.h>
#include <math_constants.h>

#define NS     16
#define NP     2048
#define DIMS   64
#define KNN    16
#define TI     32    // one warp per block
#define TJ     32    // j-rows per shared tile
#define SPLIT  2
#define JRANGE (NP / SPLIT)   // 1024
#define BUF    4     // candidate buffer slots per lane
#define TKS    17    // per-lane top-K smem stride (conflict-free)
#define SJP    (DIMS / 4 + 1) // padded tile row stride in ulonglong2 (odd -> spread banks)

typedef unsigned long long ull;

// partial top-K scratch: [half][(b*NP+i)*KNN + k]
__device__ float g_pd[SPLIT][NS * NP * KNN];
__device__ int   g_pi[SPLIT][NS * NP * KNN];

__device__ __forceinline__ void upk(float &lo, float &hi_, ull v) {
    asm("mov.b64 {%0, %1}, %2;" : "=f"(lo), "=f"(hi_) : "l"(v));
}
__device__ __forceinline__ void ffma2(ull &d, ull a, ull b) {
    asm("fma.rn.f32x2 %0, %1, %2, %3;" : "=l"(d) : "l"(a), "l"(b), "l"(d));
}
__device__ __forceinline__ void fadd2(ull &d, ull a, ull b) {
    asm("add.rn.f32x2 %0, %1, %2;" : "=l"(d) : "l"(a), "l"(b));
}

// replace-max insert into unsorted top-K kept in SMEM (per-lane region)
__device__ __forceinline__ void insert16s(float* myd, int* myi,
                                          float &worst, int &wslot,
                                          float d, int j) {
    if (d < worst) {
        myd[wslot] = d;
        myi[wslot] = j;
        float mv = myd[0]; int mj = myi[0]; int ms = 0;
        #pragma unroll
        for (int k = 1; k < KNN; ++k) {
            float vk = myd[k]; int ik = myi[k];
            bool g = (vk > mv) || (vk == mv && ik > mj);
            if (g) { mv = vk; mj = ik; ms = k; }
        }
        worst = mv; wslot = ms;
    }
}

__global__ __launch_bounds__(TI, 14)   // cap 146 regs
void knn_part(const float* __restrict__ h) {
    const int lane = threadIdx.x;
    const int b = blockIdx.x;
    const int i = blockIdx.y * TI + lane;
    const int z = blockIdx.z;                       // j-half
    const float* __restrict__ hb = h + (size_t)b * NP * DIMS;

    __shared__ ull sj[TJ * SJP * 2];          // padded tile (~8.7 KB), rows of 17 ulonglong2
    __shared__ float sx2[TJ];
    __shared__ float sbd[TI * TKS];           // per-lane top-K dists
    __shared__ int   sbi[TI * TKS];           // per-lane top-K indices

    float* myd = &sbd[lane * TKS];
    int*   myi = &sbi[lane * TKS];
    #pragma unroll
    for (int k = 0; k < KNN; ++k) { myd[k] = CUDART_INF_F; myi[k] = 0x7fffffff; }

    // ---- this thread's i-row, packed as f32x2 pairs ----
    ull hr[DIMS / 2];
    const ulonglong2* hrow = reinterpret_cast<const ulonglong2*>(hb + (size_t)i * DIMS);
    #pragma unroll
    for (int d = 0; d < DIMS / 4; ++d) { ulonglong2 t = hrow[d]; hr[2*d] = t.x; hr[2*d+1] = t.y; }
    float x2i = 0.0f;
    #pragma unroll
    for (int d = 0; d < DIMS / 2; ++d) { float a, c; upk(a, c, hr[d]); x2i += a*a + c*c; }

    float worst = CUDART_INF_F; int wslot = 0;

    // ---- candidate buffer ----
    float cd[BUF]; int cj[BUF]; int c = 0;
    #pragma unroll
    for (int s = 0; s < BUF; ++s) { cd[s] = 0.f; cj[s] = 0; }

    const int jend = (z + 1) * JRANGE;
    for (int j0 = z * JRANGE; j0 < jend; j0 += TJ) {
        __syncwarp();
        // cooperative tile load (128-bit) into padded rows
        {
            const ulonglong2* g4 = reinterpret_cast<const ulonglong2*>(hb + (size_t)j0 * DIMS);
            #pragma unroll
            for (int u = 0; u < TJ * DIMS / 4 / TI; ++u) {
                int t   = u * TI + lane;           // flat ulonglong2 index
                int row = t >> 4, cc = t & 15;
                *reinterpret_cast<ulonglong2*>(&sj[(row * SJP + cc) * 2]) = g4[t];
            }
        }
        __syncwarp();
        // ||h_j||^2 for the tile (1 row per lane; padded stride -> 4-way max conflict)
        {
            float s = 0.0f;
            const ulonglong2* rowp = reinterpret_cast<const ulonglong2*>(&sj[lane * SJP * 2]);
            #pragma unroll
            for (int d = 0; d < DIMS / 4; ++d) {
                ulonglong2 v = rowp[d];
                float a, bq, cq, e; upk(a, bq, v.x); upk(cq, e, v.y);
                s += a*a + bq*bq + cq*cq + e*e;
            }
            sx2[lane] = s;
        }
        __syncwarp();

        for (int jj = 0; jj < TJ; jj += 2) {
            // two j-rows per iteration, 2 accumulator chains each (4 chains in flight)
            const ull* r0 = &sj[(jj)     * SJP * 2];
            const ull* r1 = &sj[(jj + 1) * SJP * 2];
            ull p0 = 0ull, p1 = 0ull, q0 = 0ull, q1 = 0ull;
            #pragma unroll
            for (int d = 0; d < DIMS / 4; ++d) {
                ulonglong2 v = *reinterpret_cast<const ulonglong2*>(&r0[2*d]);
                ulonglong2 w = *reinterpret_cast<const ulonglong2*>(&r1[2*d]);
                ffma2(p0, hr[2*d],     v.x);
                ffma2(p1, hr[2*d + 1], v.y);
                ffma2(q0, hr[2*d],     w.x);
                ffma2(q1, hr[2*d + 1], w.y);
            }
            fadd2(p0, p0, p1);
            fadd2(q0, q0, q1);
            float e0, e1, e2, e3;
            upk(e0, e1, p0); upk(e2, e3, q0);
            const float dist0 = fmaf(-2.0f, e0 + e1, x2i + sx2[jj]);
            const float dist1 = fmaf(-2.0f, e2 + e3, x2i + sx2[jj + 1]);
            const int   jg0   = j0 + jj;

            // branchless filter into buffer (strict <; ascending j handles ties)
            {
                const bool t0 = dist0 < worst;
                #pragma unroll
                for (int s = 0; s < BUF; ++s)
                    if (s == c && t0) { cd[s] = dist0; cj[s] = jg0; }
                c += t0;
                const bool t1 = dist1 < worst;
                #pragma unroll
                for (int s = 0; s < BUF; ++s)
                    if (s == c && t1) { cd[s] = dist1; cj[s] = jg0 + 1; }
                c += t1;
            }
            // rare warp-wide drain (threshold BUF-1: a pair adds at most 2 from c<=BUF-2)
            if (__any_sync(0xffffffffu, c >= BUF - 1)) {
                #pragma unroll
                for (int s = 0; s < BUF; ++s) {
                    if (s < c) insert16s(myd, myi, worst, wslot, cd[s], cj[s]);
                }
                c = 0;
            }
        }
    }
    // final drain
    #pragma unroll
    for (int s = 0; s < BUF; ++s) {
        if (s < c) insert16s(myd, myi, worst, wslot, cd[s], cj[s]);
    }

    // ---- emit partial (unsorted) to scratch ----
    const size_t base = ((size_t)b * NP + i) * KNN;
    #pragma unroll
    for (int k = 0; k < KNN; ++k) {
        g_pd[z][base + k] = myd[k];
        g_pi[z][base + k] = myi[k];
    }
}

__global__ __launch_bounds__(128)
void knn_merge(float* __restrict__ out) {
    const int r = blockIdx.x * 128 + threadIdx.x;   // global row = b*NP + i
    const int b = r / NP;
    const int i = r - b * NP;

    float fd[KNN]; int fi[KNN];
    #pragma unroll
    for (int k = 0; k < KNN; ++k) { fd[k] = CUDART_INF_F; fi[k] = 0x7fffffff; }
    float wst = CUDART_INF_F; int wsl = 0;

    const size_t base = (size_t)r * KNN;
    #pragma unroll
    for (int z = 0; z < SPLIT; ++z) {
        float4 dv[4]; int4 jv[4];
        #pragma unroll
        for (int u = 0; u < 4; ++u) {
            dv[u] = *reinterpret_cast<const float4*>(&g_pd[z][base + 4 * u]);
            jv[u] = *reinterpret_cast<const int4*>  (&g_pi[z][base + 4 * u]);
        }
        const float* dp = reinterpret_cast<const float*>(dv);
        const int*   jp = reinterpret_cast<const int*>(jv);
        #pragma unroll
        for (int k = 0; k < KNN; ++k) {
            float d = dp[k];
            int   j = jp[k];
            if (d < wst || (d == wst && j < fi[wsl])) {
                #pragma unroll
                for (int s = 0; s < KNN; ++s)
                    if (s == wsl) { fd[s] = d; fi[s] = j; }
                float mv = fd[0]; int mj = fi[0]; int ms = 0;
                #pragma unroll
                for (int s = 1; s < KNN; ++s) {
                    bool g = (fd[s] > mv) || (fd[s] == mv && fi[s] > mj);
                    if (g) { mv = fd[s]; mj = fi[s]; ms = s; }
                }
                wst = mv; wsl = ms;
            }
        }
    }
    // sort ascending by (dist, idx): odd-even, 16 passes
    #pragma unroll
    for (int p = 0; p < KNN; ++p) {
        #pragma unroll
        for (int k = (p & 1); k + 1 < KNN; k += 2) {
            bool sw = (fd[k] > fd[k + 1]) || (fd[k] == fd[k + 1] && fi[k] > fi[k + 1]);
            if (sw) {
                float td = fd[k]; fd[k] = fd[k + 1]; fd[k + 1] = td;
                int   ti = fi[k]; fi[k] = fi[k + 1]; fi[k + 1] = ti;
            }
        }
    }
    // emit [knn_dist | dst | src]
    const size_t sect = (size_t)NS * NP * KNN;
    float* od   = out + base;
    float* odst = out + sect + base;
    float* osrc = out + 2 * sect + base;
    const int off = b * NP;
    #pragma unroll
    for (int k = 0; k < KNN; ++k) {
        od[k]   = fd[k];
        odst[k] = (float)(fi[k] + off);
        osrc[k] = (float)(i + off);
    }
}

extern "C" void kernel_launch(void* const* d_in, const int* in_sizes, int n_in,
                              void* d_out, int out_size) {
    (void)in_sizes; (void)n_in; (void)out_size;
    const float* h = (const float*)d_in[0];   // (16, 2048, 64) fp32; K=16 hardcoded
    float* out = (float*)d_out;
    dim3 g1(NS, NP / TI, SPLIT);
    knn_part<<<g1, TI>>>(h);
    knn_merge<<<(NS * NP) / 128, 128>>>(out);
}

// round 16
// speedup vs baseline: 21.3024x; 1.0011x over previous
#include <cuda_runtime.h>
#include <math_constants.h>

#define NS     16
#define NP     2048
#define DIMS   64
#define KNN    16
#define TI     32    // one warp per block
#define TJ     32    // j-rows per shared tile
#define SPLIT  2
#define JRANGE (NP / SPLIT)   // 1024
#define BUF    8     // candidate buffer slots per lane
#define TKS    17    // per-lane top-K smem stride (conflict-free)
#define SJP    (DIMS / 4 + 1) // padded tile row stride in ulonglong2

typedef unsigned long long ull;

// partial top-K scratch: [half][(b*NP+i)*KNN + k]
__device__ float g_pd[SPLIT][NS * NP * KNN];
__device__ int   g_pi[SPLIT][NS * NP * KNN];

__device__ __forceinline__ void upk(float &lo, float &hi_, ull v) {
    asm("mov.b64 {%0, %1}, %2;" : "=f"(lo), "=f"(hi_) : "l"(v));
}
__device__ __forceinline__ void ffma2(ull &d, ull a, ull b) {
    asm("fma.rn.f32x2 %0, %1, %2, %3;" : "=l"(d) : "l"(a), "l"(b), "l"(d));
}
__device__ __forceinline__ void fadd2(ull &d, ull a, ull b) {
    asm("add.rn.f32x2 %0, %1, %2;" : "=l"(d) : "l"(a), "l"(b));
}

// replace-max insert into unsorted top-K kept in SMEM (per-lane region)
__device__ __forceinline__ void insert16s(float* myd, int* myi,
                                          float &worst, int &wslot,
                                          float d, int j) {
    if (d < worst) {
        myd[wslot] = d;
        myi[wslot] = j;
        float mv = myd[0]; int mj = myi[0]; int ms = 0;
        #pragma unroll
        for (int k = 1; k < KNN; ++k) {
            float vk = myd[k]; int ik = myi[k];
            bool g = (vk > mv) || (vk == mv && ik > mj);
            if (g) { mv = vk; mj = ik; ms = k; }
        }
        worst = mv; wslot = ms;
    }
}

__global__ __launch_bounds__(TI, 14)   // cap 146 regs
void knn_part(const float* __restrict__ h) {
    const int lane = threadIdx.x;
    const int b = blockIdx.x;
    const int i = blockIdx.y * TI + lane;
    const int z = blockIdx.z;                       // j-half
    const float* __restrict__ hb = h + (size_t)b * NP * DIMS;

    __shared__ ull sj[TJ * SJP * 2];          // padded tile (~8.7 KB)
    __shared__ float sx2[TJ];
    __shared__ float sbd[TI * TKS];           // per-lane top-K dists (on m = x2j - 2 dot)
    __shared__ int   sbi[TI * TKS];

    float* myd = &sbd[lane * TKS];
    int*   myi = &sbi[lane * TKS];
    #pragma unroll
    for (int k = 0; k < KNN; ++k) { myd[k] = CUDART_INF_F; myi[k] = 0x7fffffff; }

    // ---- this thread's i-row, packed as f32x2 pairs + ||h_i||^2 ----
    ull hr[DIMS / 2];
    const ulonglong2* hrow = reinterpret_cast<const ulonglong2*>(hb + (size_t)i * DIMS);
    #pragma unroll
    for (int d = 0; d < DIMS / 4; ++d) { ulonglong2 t = hrow[d]; hr[2*d] = t.x; hr[2*d+1] = t.y; }
    float x2i = 0.0f;
    #pragma unroll
    for (int d = 0; d < DIMS / 2; ++d) { float a, c; upk(a, c, hr[d]); x2i += a*a + c*c; }

    float worst = CUDART_INF_F; int wslot = 0;

    // ---- candidate buffer ----
    float cd[BUF]; int cj[BUF]; int c = 0;
    #pragma unroll
    for (int s = 0; s < BUF; ++s) { cd[s] = 0.f; cj[s] = 0; }

    const int jend = (z + 1) * JRANGE;
    for (int j0 = z * JRANGE; j0 < jend; j0 += TJ) {
        __syncwarp();
        // cooperative tile load (128-bit) into padded rows
        {
            const ulonglong2* g4 = reinterpret_cast<const ulonglong2*>(hb + (size_t)j0 * DIMS);
            #pragma unroll
            for (int u = 0; u < TJ * DIMS / 4 / TI; ++u) {
                int t   = u * TI + lane;
                int row = t >> 4, cc = t & 15;
                *reinterpret_cast<ulonglong2*>(&sj[(row * SJP + cc) * 2]) = g4[t];
            }
        }
        __syncwarp();
        // ||h_j||^2 for the tile (1 row per lane; padded stride)
        {
            float s = 0.0f;
            const ulonglong2* rowp = reinterpret_cast<const ulonglong2*>(&sj[lane * SJP * 2]);
            #pragma unroll
            for (int d = 0; d < DIMS / 4; ++d) {
                ulonglong2 v = rowp[d];
                float a, bq, cq, e; upk(a, bq, v.x); upk(cq, e, v.y);
                s += a*a + bq*bq + cq*cq + e*e;
            }
            sx2[lane] = s;
        }
        __syncwarp();

        for (int jj = 0; jj < TJ; jj += 4) {
            // four j-rows per iteration, 2 accumulator chains each (8 chains in flight)
            const ull* r0 = &sj[(jj)     * SJP * 2];
            const ull* r1 = &sj[(jj + 1) * SJP * 2];
            const ull* r2 = &sj[(jj + 2) * SJP * 2];
            const ull* r3 = &sj[(jj + 3) * SJP * 2];
            ull p0 = 0ull, p1 = 0ull, q0 = 0ull, q1 = 0ull;
            ull s0 = 0ull, s1 = 0ull, t0 = 0ull, t1 = 0ull;
            #pragma unroll
            for (int d = 0; d < DIMS / 4; ++d) {
                ulonglong2 v0 = *reinterpret_cast<const ulonglong2*>(&r0[2*d]);
                ulonglong2 v1 = *reinterpret_cast<const ulonglong2*>(&r1[2*d]);
                ulonglong2 v2 = *reinterpret_cast<const ulonglong2*>(&r2[2*d]);
                ulonglong2 v3 = *reinterpret_cast<const ulonglong2*>(&r3[2*d]);
                ffma2(p0, hr[2*d],     v0.x);
                ffma2(p1, hr[2*d + 1], v0.y);
                ffma2(q0, hr[2*d],     v1.x);
                ffma2(q1, hr[2*d + 1], v1.y);
                ffma2(s0, hr[2*d],     v2.x);
                ffma2(s1, hr[2*d + 1], v2.y);
                ffma2(t0, hr[2*d],     v3.x);
                ffma2(t1, hr[2*d + 1], v3.y);
            }
            fadd2(p0, p0, p1);
            fadd2(q0, q0, q1);
            fadd2(s0, s0, s1);
            fadd2(t0, t0, t1);
            float e0, e1, e2, e3, e4, e5, e6, e7;
            upk(e0, e1, p0); upk(e2, e3, q0); upk(e4, e5, s0); upk(e6, e7, t0);
            // rank on m = x2j - 2*dot (x2i added at emit)
            const float m0 = fmaf(-2.0f, e0 + e1, sx2[jj]);
            const float m1 = fmaf(-2.0f, e2 + e3, sx2[jj + 1]);
            const float m2 = fmaf(-2.0f, e4 + e5, sx2[jj + 2]);
            const float m3 = fmaf(-2.0f, e6 + e7, sx2[jj + 3]);
            const int   jg = j0 + jj;

            // branchless filter into buffer (strict <; ascending j handles ties)
            {
                const bool f0 = m0 < worst;
                #pragma unroll
                for (int s = 0; s < BUF; ++s)
                    if (s == c && f0) { cd[s] = m0; cj[s] = jg; }
                c += f0;
                const bool f1 = m1 < worst;
                #pragma unroll
                for (int s = 0; s < BUF; ++s)
                    if (s == c && f1) { cd[s] = m1; cj[s] = jg + 1; }
                c += f1;
                const bool f2 = m2 < worst;
                #pragma unroll
                for (int s = 0; s < BUF; ++s)
                    if (s == c && f2) { cd[s] = m2; cj[s] = jg + 2; }
                c += f2;
                const bool f3 = m3 < worst;
                #pragma unroll
                for (int s = 0; s < BUF; ++s)
                    if (s == c && f3) { cd[s] = m3; cj[s] = jg + 3; }
                c += f3;
            }
            // one vote per quad; drain keeps >=4 free slots for the next quad
            if (__any_sync(0xffffffffu, c >= BUF - 3)) {
                #pragma unroll
                for (int s = 0; s < BUF; ++s) {
                    if (s < c) insert16s(myd, myi, worst, wslot, cd[s], cj[s]);
                }
                c = 0;
            }
        }
    }
    // final drain
    #pragma unroll
    for (int s = 0; s < BUF; ++s) {
        if (s < c) insert16s(myd, myi, worst, wslot, cd[s], cj[s]);
    }

    // ---- emit partial (unsorted, true dist = x2i + m) ----
    const size_t base = ((size_t)b * NP + i) * KNN;
    #pragma unroll
    for (int k = 0; k < KNN; ++k) {
        g_pd[z][base + k] = x2i + myd[k];
        g_pi[z][base + k] = myi[k];
    }
}

__global__ __launch_bounds__(128)
void knn_merge(float* __restrict__ out) {
    const int r = blockIdx.x * 128 + threadIdx.x;   // global row = b*NP + i
    const int b = r / NP;
    const int i = r - b * NP;

    float fd[KNN]; int fi[KNN];
    #pragma unroll
    for (int k = 0; k < KNN; ++k) { fd[k] = CUDART_INF_F; fi[k] = 0x7fffffff; }
    float wst = CUDART_INF_F; int wsl = 0;

    const size_t base = (size_t)r * KNN;
    #pragma unroll
    for (int z = 0; z < SPLIT; ++z) {
        float4 dv[4]; int4 jv[4];
        #pragma unroll
        for (int u = 0; u < 4; ++u) {
            dv[u] = *reinterpret_cast<const float4*>(&g_pd[z][base + 4 * u]);
            jv[u] = *reinterpret_cast<const int4*>  (&g_pi[z][base + 4 * u]);
        }
        const float* dp = reinterpret_cast<const float*>(dv);
        const int*   jp = reinterpret_cast<const int*>(jv);
        #pragma unroll
        for (int k = 0; k < KNN; ++k) {
            float d = dp[k];
            int   j = jp[k];
            if (d < wst || (d == wst && j < fi[wsl])) {
                #pragma unroll
                for (int s = 0; s < KNN; ++s)
                    if (s == wsl) { fd[s] = d; fi[s] = j; }
                float mv = fd[0]; int mj = fi[0]; int ms = 0;
                #pragma unroll
                for (int s = 1; s < KNN; ++s) {
                    bool g = (fd[s] > mv) || (fd[s] == mv && fi[s] > mj);
                    if (g) { mv = fd[s]; mj = fi[s]; ms = s; }
                }
                wst = mv; wsl = ms;
            }
        }
    }
    // sort ascending by (dist, idx): odd-even, 16 passes
    #pragma unroll
    for (int p = 0; p < KNN; ++p) {
        #pragma unroll
        for (int k = (p & 1); k + 1 < KNN; k += 2) {
            bool sw = (fd[k] > fd[k + 1]) || (fd[k] == fd[k + 1] && fi[k] > fi[k + 1]);
            if (sw) {
                float td = fd[k]; fd[k] = fd[k + 1]; fd[k + 1] = td;
                int   ti = fi[k]; fi[k] = fi[k + 1]; fi[k + 1] = ti;
            }
        }
    }
    // emit [knn_dist | dst | src]
    const size_t sect = (size_t)NS * NP * KNN;
    float* od   = out + base;
    float* odst = out + sect + base;
    float* osrc = out + 2 * sect + base;
    const int off = b * NP;
    #pragma unroll
    for (int k = 0; k < KNN; ++k) {
        od[k]   = fd[k];
        odst[k] = (float)(fi[k] + off);
        osrc[k] = (float)(i + off);
    }
}

extern "C" void kernel_launch(void* const* d_in, const int* in_sizes, int n_in,
                              void* d_out, int out_size) {
    (void)in_sizes; (void)n_in; (void)out_size;
    const float* h = (const float*)d_in[0];   // (16, 2048, 64) fp32; K=16 hardcoded
    float* out = (float*)d_out;
    dim3 g1(NS, NP / TI, SPLIT);
    knn_part<<<g1, TI>>>(h);
    knn_merge<<<(NS * NP) / 128, 128>>>(out);
}